// round 16
// baseline (speedup 1.0000x reference)
#include <cuda_runtime.h>
#include <cuda_fp16.h>
#include <math.h>
#include <stdint.h>

#define LQ 1024
#define BZ 8
#define D  512
#define NH 8
#define DH 64
#define IOU_THR 0.2f
#define COS_THR 0.2f
#define NEGF -3.402823466e38f

#define SSTRH 72  // fp16 stride (halves): 144B -> LDSM conflict-free

// ---------------- scratch (static device globals; no allocations) ----------
__device__ __half g_hh[(size_t)BZ * LQ * D];          // fp16 h (proj A + mask A/B)
__device__ __half g_Wh[3 * 512 * 512];                // fp16 Wq|Wk|Wv
__device__ __half g_Qh[(size_t)BZ * LQ * D];
__device__ __half g_Kh[(size_t)BZ * LQ * D];
__device__ __half g_Vth[(size_t)BZ * NH * DH * LQ];   // [bh][dh][Lq]
__device__ float  g_norm[BZ * LQ];
__device__ unsigned char g_mask[(size_t)BZ * LQ * LQ];
__device__ unsigned char g_live[BZ * 8 * 16];

__device__ __forceinline__ uint32_t smem_u32(const void* p) {
    uint32_t a;
    asm("{ .reg .u64 t; cvta.to.shared.u64 t, %1; cvt.u32.u64 %0, t; }"
        : "=r"(a) : "l"(p));
    return a;
}
__device__ __forceinline__ uint32_t pack_h2(float lo, float hi) {
    __half2 h = __floats2half2_rn(lo, hi);
    return *(uint32_t*)&h;
}

#define MMA_F16(c0, c1, c2, c3, a0, a1, a2, a3, b0, b1) \
    asm volatile("mma.sync.aligned.m16n8k16.row.col.f32.f16.f16.f32 " \
        "{%0,%1,%2,%3}, {%4,%5,%6,%7}, {%8,%9}, {%0,%1,%2,%3};" \
        : "+f"(c0), "+f"(c1), "+f"(c2), "+f"(c3) \
        : "r"(a0), "r"(a1), "r"(a2), "r"(a3), "r"(b0), "r"(b1))

#define LDSM_X4(d0, d1, d2, d3, addr) \
    asm volatile("ldmatrix.sync.aligned.m8n8.x4.shared.b16 {%0,%1,%2,%3}, [%4];" \
        : "=r"(d0), "=r"(d1), "=r"(d2), "=r"(d3) : "r"(addr))

#define CPASYNC16(dst, src) \
    asm volatile("cp.async.ca.shared.global [%0], [%1], 16;" \
                 :: "r"(dst), "l"(src) : "memory")
#define CPCOMMIT() asm volatile("cp.async.commit_group;" ::: "memory")
#define CPWAIT(n)  asm volatile("cp.async.wait_group %0;" :: "n"(n) : "memory")

__device__ __forceinline__ float warp_sum(float v) {
#pragma unroll
    for (int o = 16; o > 0; o >>= 1) v += __shfl_xor_sync(0xffffffffu, v, o);
    return v;
}

#define CHUNK_BYTES 18432   // 128 rows * 72 halves * 2B

// ==================== fp16 GEMM core (K64 chunks, 2-stage) ==================
__device__ __forceinline__ void mma_chunk_h(uint32_t As_u, uint32_t Bs_u,
                                            int wm, int wn, int lane,
                                            float (&acc)[4][4][4]) {
    const uint32_t a_base = As_u +
        ((wm * 64 + (lane & 15)) * SSTRH + ((lane >> 4) & 1) * 8) * 2;
    const uint32_t b_base = Bs_u +
        (((wn * 4 + ((lane >> 4) & 1)) * 8 + (lane & 7)) * SSTRH + ((lane >> 3) & 1) * 8) * 2;
#pragma unroll
    for (int ks = 0; ks < 4; ks++) {       // each ks = k16
        uint32_t a[4][4];
#pragma unroll
        for (int mf = 0; mf < 4; mf++)
            LDSM_X4(a[mf][0], a[mf][1], a[mf][2], a[mf][3],
                    a_base + (mf * 16 * SSTRH) * 2 + ks * 32);
        uint32_t bfr[2][4];
#pragma unroll
        for (int p = 0; p < 2; p++)
            LDSM_X4(bfr[p][0], bfr[p][1], bfr[p][2], bfr[p][3],
                    b_base + (p * 16 * SSTRH) * 2 + ks * 32);
#pragma unroll
        for (int mf = 0; mf < 4; mf++)
#pragma unroll
            for (int nf = 0; nf < 4; nf++)
                MMA_F16(acc[mf][nf][0], acc[mf][nf][1], acc[mf][nf][2], acc[mf][nf][3],
                        a[mf][0], a[mf][1], a[mf][2], a[mf][3],
                        bfr[nf >> 1][(nf & 1) * 2], bfr[nf >> 1][(nf & 1) * 2 + 1]);
    }
}

__device__ __forceinline__ void issue_chunk_h(uint32_t base,
                                              const __half* __restrict__ Ab, int Astr,
                                              const __half* __restrict__ Bb, int Bstr,
                                              int it, int tid) {
    const int p = it & 1;
    const uint32_t aoff = base + (uint32_t)(p * CHUNK_BYTES);
    const uint32_t boff = base + (uint32_t)((2 + p) * CHUNK_BYTES);
#pragma unroll
    for (int i = 0; i < 4; i++) {
        int idx = tid + i * 256;
        int r = idx >> 3, c8 = idx & 7;
        CPASYNC16(aoff + (r * SSTRH + c8 * 8) * 2, Ab + (size_t)r * Astr + it * 64 + c8 * 8);
        CPASYNC16(boff + (r * SSTRH + c8 * 8) * 2, Bb + (size_t)r * Bstr + it * 64 + c8 * 8);
    }
}

template <int NCH>
__device__ __forceinline__ void gemm_h(const __half* __restrict__ Ab, int Astr,
                                       const __half* __restrict__ Bb, int Bstr,
                                       float* smem, float (&acc)[4][4][4]) {
    const int tid = threadIdx.x;
    const int w = tid >> 5, lane = tid & 31;
    const int wm = w & 1, wn = w >> 1;
    const uint32_t base = smem_u32(smem);
    issue_chunk_h(base, Ab, Astr, Bb, Bstr, 0, tid);
    CPCOMMIT();
    for (int it = 0; it < NCH; ++it) {
        const int p = it & 1;
        CPWAIT(0);
        __syncthreads();
        if (it + 1 < NCH) {
            issue_chunk_h(base, Ab, Astr, Bb, Bstr, it + 1, tid);
            CPCOMMIT();
        }
        mma_chunk_h(base + p * CHUNK_BYTES, base + (2 + p) * CHUNK_BYTES,
                    wm, wn, lane, acc);
    }
    __syncthreads();
}

// ---------------- prep: norms + fp16 h + fp16 W -----------------------------
__global__ void prep_kernel(const float* __restrict__ q,
                            const float* __restrict__ Wq,
                            const float* __restrict__ Wk,
                            const float* __restrict__ Wv) {
    const int bid = blockIdx.x, tid = threadIdx.x;
    if (bid < 4096) {
        const int half_ = tid >> 7;
        const int t = tid & 127;
        const int row = bid * 2 + half_;
        const int b = row >> 10, l = row & 1023;
        const size_t o = ((size_t)l * BZ + b) * D + t * 4;
        float4 v = *(const float4*)(q + o);
        *(__half2*)(g_hh + o)     = __floats2half2_rn(v.x, v.y);
        *(__half2*)(g_hh + o + 2) = __floats2half2_rn(v.z, v.w);
        float s = v.x * v.x + v.y * v.y + v.z * v.z + v.w * v.w;
        s = warp_sum(s);
        __shared__ float red[8];
        if ((t & 31) == 0) red[half_ * 4 + (t >> 5)] = s;
        __syncthreads();
        if (t == 0) {
            float tot = red[half_ * 4] + red[half_ * 4 + 1] +
                        red[half_ * 4 + 2] + red[half_ * 4 + 3];
            g_norm[row] = fmaxf(sqrtf(tot), 1e-8f);
        }
    } else {
        const int idx = (bid - 4096) * 256 + tid;
        const int which = idx >> 16;
        const int off = (idx & 65535) * 4;
        const float* W = (which == 0) ? Wq : (which == 1) ? Wk : Wv;
        float4 v = *(const float4*)(W + off);
        __half* dst = g_Wh + which * 262144 + off;
        *(__half2*)(dst)     = __floats2half2_rn(v.x, v.y);
        *(__half2*)(dst + 2) = __floats2half2_rn(v.z, v.w);
    }
}

// ================ fused proj (bid<768) + mask (bid>=768), all fp16 ==========
__global__ __launch_bounds__(256, 2) void pm_kernel(
    const float* __restrict__ seg,
    const float* __restrict__ bq, const float* __restrict__ bk, const float* __restrict__ bv) {
    extern __shared__ float smp[];
    const int tid = threadIdx.x;
    const int w = tid >> 5, lane = tid & 31;
    const int wm = w & 1, wn = w >> 1;
    const int bid = blockIdx.x;

    if (bid < 768) {   // ---------------- projection path ----------------
        const int which = bid >> 8;
        const int rem = bid & 255;
        const int col0 = (rem & 3) * 128;
        const int y = rem >> 2;
        const int b = y >> 3;
        const int i0 = (y & 7) * 128;
        const float* bias = (which == 0) ? bq : (which == 1) ? bk : bv;

        float acc[4][4][4] = {};
        const __half* Ab = g_hh + (size_t)i0 * (BZ * D) + (size_t)b * D;
        const __half* Bb = g_Wh + which * 262144 + (size_t)col0 * D;
        gemm_h<D / 64>(Ab, BZ * D, Bb, D, smp, acc);

        const int rbase = wm * 64 + (lane >> 2);
        const int cbase = wn * 32 + (lane & 3) * 2;
        if (which < 2) {
            __half* out = (which == 0) ? g_Qh : g_Kh;
#pragma unroll
            for (int mf = 0; mf < 4; mf++) {
                int r0 = i0 + rbase + mf * 16;
#pragma unroll
                for (int nf = 0; nf < 4; nf++) {
                    int c = col0 + cbase + nf * 8;
                    float2 bb = *(const float2*)&bias[c];
                    *(__half2*)&out[((size_t)(b * LQ + r0)) * D + c] =
                        __floats2half2_rn(acc[mf][nf][0] + bb.x, acc[mf][nf][1] + bb.y);
                    *(__half2*)&out[((size_t)(b * LQ + r0 + 8)) * D + c] =
                        __floats2half2_rn(acc[mf][nf][2] + bb.x, acc[mf][nf][3] + bb.y);
                }
            }
        } else {
#pragma unroll
            for (int mf = 0; mf < 4; mf++) {
                int r0 = i0 + rbase + mf * 16;
#pragma unroll
                for (int nf = 0; nf < 4; nf++) {
                    int n = col0 + cbase + nf * 8;
                    float2 bb = *(const float2*)&bias[n];
                    size_t o0 = ((size_t)(b * NH + (n >> 6)) * DH + (n & 63)) * LQ;
                    size_t o1 = ((size_t)(b * NH + ((n + 1) >> 6)) * DH + ((n + 1) & 63)) * LQ;
                    g_Vth[o0 + r0]     = __float2half_rn(acc[mf][nf][0] + bb.x);
                    g_Vth[o1 + r0]     = __float2half_rn(acc[mf][nf][1] + bb.y);
                    g_Vth[o0 + r0 + 8] = __float2half_rn(acc[mf][nf][2] + bb.x);
                    g_Vth[o1 + r0 + 8] = __float2half_rn(acc[mf][nf][3] + bb.y);
                }
            }
        }
    } else {   // -------- mask path (fp16): I<=J triangle -------------------
        const int mb = bid - 768;
        const int b = mb / 36;
        int t = mb % 36;
        int I = 0;
        while (t >= 8 - I) { t -= 8 - I; I++; }
        const int J = I + t;
        const int i0 = I * 128, j0 = J * 128;

        float acc[4][4][4] = {};
        const __half* Ab = g_hh + (size_t)i0 * (BZ * D) + (size_t)b * D;
        const __half* Bb = g_hh + (size_t)j0 * (BZ * D) + (size_t)b * D;
        gemm_h<D / 64>(Ab, BZ * D, Bb, BZ * D, smp, acc);

        __shared__ unsigned int liveflag[4];   // [0,1]=col halves, [2,3]=row halves
        if (tid < 4) liveflag[tid] = 0;
        __syncthreads();

        float4* auxr = (float4*)smp;                          // [0, 2048) B
        float4* auxc = (float4*)(smp + 512);                  // [2048, 4096) B
        unsigned char* sD = (unsigned char*)(smp + 1024);     // [4096, 22528) direct 128x144
        unsigned char* sT = (unsigned char*)(smp + 5632);     // [22528, 40960) transposed
        const float* sgb = seg + (size_t)b * LQ * 2;
        if (tid < 128) {
            int r = i0 + tid;
            float2 sg = *(const float2*)(sgb + r * 2);
            auxr[tid] = make_float4(g_norm[b * LQ + r], sg.x - 0.5f * sg.y,
                                    sg.x + 0.5f * sg.y, sg.y);
        } else {
            int tt = tid - 128;
            int c = j0 + tt;
            float2 sg = *(const float2*)(sgb + c * 2);
            auxc[tt] = make_float4(g_norm[b * LQ + c], sg.x - 0.5f * sg.y,
                                   sg.x + 0.5f * sg.y, sg.y);
        }
        __syncthreads();

        const int rbase = wm * 64 + (lane >> 2);
        const int cbase = wn * 32 + (lane & 3) * 2;
        unsigned int any = 0;
#pragma unroll
        for (int mf = 0; mf < 4; mf++) {
#pragma unroll
            for (int half_ = 0; half_ < 2; half_++) {
                int rl_ = rbase + mf * 16 + half_ * 8;
                float4 ar = auxr[rl_];
                int rg = i0 + rl_;
#pragma unroll
                for (int nf = 0; nf < 4; nf++) {
                    int cl_ = cbase + nf * 8;
#pragma unroll
                    for (int e = 0; e < 2; e++) {
                        float4 ac = auxc[cl_ + e];
                        float cosv = acc[mf][nf][half_ * 2 + e] / (ar.x * ac.x);
                        float inter = fmaxf(fminf(ar.z, ac.z) - fmaxf(ar.y, ac.y), 0.f);
                        float iou = inter / (ar.w + ac.w - inter);
                        int cg = j0 + cl_ + e;
                        bool adj = (cosv > COS_THR) && ((iou <= IOU_THR) || (rg == cg));
                        any |= (unsigned)adj;
                        unsigned char mv = adj ? 0 : 1;
                        sD[rl_ * 144 + cl_ + e] = mv;         // direct stage
                        sT[(cl_ + e) * 144 + rl_] = mv;       // transposed stage
                    }
                }
            }
        }
        if (any) {
            atomicOr(&liveflag[wn >> 1], 1u);
            atomicOr(&liveflag[2 + wm], 1u);
        }
        __syncthreads();

        const unsigned int tile_any = liveflag[0] | liveflag[1] |
                                      liveflag[2] | liveflag[3];
        if (tile_any) {
            // direct block: rows (b, i0+c) cols [j0, j0+128)
#pragma unroll
            for (int i = 0; i < 4; i++) {
                int idx = tid + i * 256;
                int c = idx >> 3, g = idx & 7;
                *(uint4*)&g_mask[((size_t)(b * LQ + i0 + c)) * LQ + j0 + g * 16] =
                    *(const uint4*)&sD[c * 144 + g * 16];
            }
            if (I != J) {   // transposed block
#pragma unroll
                for (int i = 0; i < 4; i++) {
                    int idx = tid + i * 256;
                    int c = idx >> 3, g = idx & 7;
                    *(uint4*)&g_mask[((size_t)(b * LQ + j0 + c)) * LQ + i0 + g * 16] =
                        *(const uint4*)&sT[c * 144 + g * 16];
                }
            }
        }
        if (I != J && tid < 2)
            g_live[(b * 8 + J) * 16 + I * 2 + tid] = (unsigned char)liveflag[2 + tid];
        if (tid < 2)
            g_live[(b * 8 + I) * 16 + J * 2 + tid] = (unsigned char)liveflag[tid];
    }
}

// ==================== fused attention (fp16 flash, diag-first) ==============
// smem halves: sQ[0,9216) sK0[9216,13824) sK1[13824,18432) sV0[18432,23040) sV1[23040,27648)
#define FSM_BYTES (27648 * 2)

__device__ __forceinline__ void issue_kv(__half* smh, int p, int jt,
                                         int b, int bh, int h, int tid) {
    const int j0 = jt * 64;
    const uint32_t koff = smem_u32(smh + 9216 + p * 4608);
    const uint32_t voff = smem_u32(smh + 18432 + p * 4608);
#pragma unroll
    for (int i = 0; i < 2; i++) {
        int idx = tid + i * 256;
        int r = idx >> 3, g = idx & 7;
        CPASYNC16(koff + (r * SSTRH + g * 8) * 2,
                  g_Kh + ((size_t)(b * LQ + j0 + r)) * D + h * DH + g * 8);
        CPASYNC16(voff + (r * SSTRH + g * 8) * 2,
                  g_Vth + ((size_t)bh * DH + r) * LQ + j0 + g * 8);
    }
}

__global__ __launch_bounds__(256, 2) void flash_kernel(const float* __restrict__ q,
                                                       float* __restrict__ out) {
    extern __shared__ __half smh[];
    const int tid = threadIdx.x;
    const int w = tid >> 5, lane = tid & 31;
    const int rr = lane >> 2, cc = lane & 3;
    const int bh = blockIdx.y, b = bh >> 3, h = bh & 7;
    const int i0 = blockIdx.x * 128;
    const int wbase = w * 16;
    const int d0 = i0 >> 6, d1 = d0 + 1;    // diagonal tiles: ALWAYS live

    __shared__ int s_list[16];
    __shared__ int s_nrest;

    // G0: Q + KV(d0); G1: KV(d1) — issued before the ballot (diag liveness static)
    {
        const uint32_t qoff = smem_u32(smh);
#pragma unroll
        for (int i = 0; i < 4; i++) {
            int idx = tid + i * 256;
            int r = idx >> 3, g = idx & 7;
            CPASYNC16(qoff + (r * SSTRH + g * 8) * 2,
                      g_Qh + ((size_t)(b * LQ + i0 + r)) * D + h * DH + g * 8);
        }
        issue_kv(smh, 0, d0, b, bh, h, tid);
        CPCOMMIT();
        issue_kv(smh, 1, d1, b, bh, h, tid);
        CPCOMMIT();
    }
    if (w == 0) {
        unsigned f = 0;
        if (lane < 16) f = g_live[(b * 8 + (i0 >> 7)) * 16 + lane];
        unsigned bal = __ballot_sync(0xffffffffu, f != 0) & 0xffffu;
        bal &= ~((1u << d0) | (1u << d1));
        if (lane < 16 && ((bal >> lane) & 1u))
            s_list[__popc(bal & ((1u << lane) - 1))] = lane;
        if (lane == 0) s_nrest = __popc(bal);
    }
    __syncthreads();
    const int ntot = 2 + s_nrest;

    const uint32_t q_base = smem_u32(smh) +
        ((wbase + (lane & 15)) * SSTRH + ((lane >> 4) & 1) * 8) * 2;
    const uint32_t fb = ((((lane >> 4) & 1) * 8 + (lane & 7)) * SSTRH +
                         ((lane >> 3) & 1) * 8) * 2;
    const uint32_t k_base0 = smem_u32(smh + 9216) + fb;
    const uint32_t v_base0 = smem_u32(smh + 18432) + fb;

    float Oacc[8][4] = {};
    float m0 = NEGF, m1 = NEGF, l0 = 0.f, l1 = 0.f;
    const int r0g = i0 + wbase + rr, r1g = r0g + 8;
    const unsigned char* mrow0 = g_mask + ((size_t)(b * LQ + r0g)) * LQ;
    const unsigned char* mrow1 = g_mask + ((size_t)(b * LQ + r1g)) * LQ;

    for (int li = 0; li < ntot; li++) {
        const int p = li & 1;
        const int jt = (li == 0) ? d0 : (li == 1) ? d1 : s_list[li - 2];
        const int j0 = jt * 64;
        if (li == 0) { CPWAIT(1); }
        else         { CPWAIT(0); }
        __syncthreads();
        if (li >= 1 && li + 1 < ntot) {
            const int njt = (li + 1 == 1) ? d1 : s_list[li - 1];
            issue_kv(smh, p ^ 1, njt, b, bh, h, tid);
            CPCOMMIT();
        }
        const uint32_t k_base = k_base0 + p * 9216;
        const uint32_t v_base = v_base0 + p * 9216;

        // S = Q K^T (fp16 m16n8k16)
        float Sacc[8][4] = {};
#pragma unroll
        for (int ks = 0; ks < 4; ks++) {
            uint32_t a0, a1, a2, a3;
            LDSM_X4(a0, a1, a2, a3, q_base + ks * 32);
#pragma unroll
            for (int pp = 0; pp < 4; pp++) {
                uint32_t f0, f1, f2, f3;
                LDSM_X4(f0, f1, f2, f3, k_base + pp * (16 * SSTRH * 2) + ks * 32);
                MMA_F16(Sacc[pp * 2][0], Sacc[pp * 2][1], Sacc[pp * 2][2], Sacc[pp * 2][3],
                        a0, a1, a2, a3, f0, f1);
                MMA_F16(Sacc[pp * 2 + 1][0], Sacc[pp * 2 + 1][1],
                        Sacc[pp * 2 + 1][2], Sacc[pp * 2 + 1][3],
                        a0, a1, a2, a3, f2, f3);
            }
        }

        // scale + mask + tile row max
        float mx0 = NEGF, mx1 = NEGF;
#pragma unroll
        for (int nf = 0; nf < 8; nf++) {
            int c = j0 + nf * 8 + cc * 2;
            uchar2 ma = *(const uchar2*)&mrow0[c];
            uchar2 mb = *(const uchar2*)&mrow1[c];
            Sacc[nf][0] = ma.x ? NEGF : Sacc[nf][0] * 0.125f;
            Sacc[nf][1] = ma.y ? NEGF : Sacc[nf][1] * 0.125f;
            Sacc[nf][2] = mb.x ? NEGF : Sacc[nf][2] * 0.125f;
            Sacc[nf][3] = mb.y ? NEGF : Sacc[nf][3] * 0.125f;
            mx0 = fmaxf(mx0, fmaxf(Sacc[nf][0], Sacc[nf][1]));
            mx1 = fmaxf(mx1, fmaxf(Sacc[nf][2], Sacc[nf][3]));
        }
        mx0 = fmaxf(mx0, __shfl_xor_sync(0xffffffffu, mx0, 1));
        mx0 = fmaxf(mx0, __shfl_xor_sync(0xffffffffu, mx0, 2));
        mx1 = fmaxf(mx1, __shfl_xor_sync(0xffffffffu, mx1, 1));
        mx1 = fmaxf(mx1, __shfl_xor_sync(0xffffffffu, mx1, 2));

        float nm0 = fmaxf(m0, mx0), nm1 = fmaxf(m1, mx1);
        float al0 = __expf(m0 - nm0), al1 = __expf(m1 - nm1);
        m0 = nm0; m1 = nm1;

        float rs0 = 0.f, rs1 = 0.f;
#pragma unroll
        for (int nf = 0; nf < 8; nf++) {
            float p00 = __expf(Sacc[nf][0] - nm0);
            float p01 = __expf(Sacc[nf][1] - nm0);
            float p10 = __expf(Sacc[nf][2] - nm1);
            float p11 = __expf(Sacc[nf][3] - nm1);
            rs0 += p00 + p01; rs1 += p10 + p11;
            Sacc[nf][0] = p00; Sacc[nf][1] = p01;
            Sacc[nf][2] = p10; Sacc[nf][3] = p11;
            Oacc[nf][0] *= al0; Oacc[nf][1] *= al0;
            Oacc[nf][2] *= al1; Oacc[nf][3] *= al1;
        }
        rs0 += __shfl_xor_sync(0xffffffffu, rs0, 1);
        rs0 += __shfl_xor_sync(0xffffffffu, rs0, 2);
        rs1 += __shfl_xor_sync(0xffffffffu, rs1, 1);
        rs1 += __shfl_xor_sync(0xffffffffu, rs1, 2);
        l0 = l0 * al0 + rs0;
        l1 = l1 * al1 + rs1;

        // O += P @ V : P packed to fp16 in registers; V frags via ldmatrix
#pragma unroll
        for (int ks = 0; ks < 4; ks++) {
            uint32_t a0 = pack_h2(Sacc[ks * 2][0], Sacc[ks * 2][1]);
            uint32_t a1 = pack_h2(Sacc[ks * 2][2], Sacc[ks * 2][3]);
            uint32_t a2 = pack_h2(Sacc[ks * 2 + 1][0], Sacc[ks * 2 + 1][1]);
            uint32_t a3 = pack_h2(Sacc[ks * 2 + 1][2], Sacc[ks * 2 + 1][3]);
#pragma unroll
            for (int pp = 0; pp < 4; pp++) {
                uint32_t f0, f1, f2, f3;
                LDSM_X4(f0, f1, f2, f3, v_base + pp * (16 * SSTRH * 2) + ks * 32);
                MMA_F16(Oacc[pp * 2][0], Oacc[pp * 2][1], Oacc[pp * 2][2], Oacc[pp * 2][3],
                        a0, a1, a2, a3, f0, f1);
                MMA_F16(Oacc[pp * 2 + 1][0], Oacc[pp * 2 + 1][1],
                        Oacc[pp * 2 + 1][2], Oacc[pp * 2 + 1][3],
                        a0, a1, a2, a3, f2, f3);
            }
        }
    }

    // epilogue
    float inv0 = 1.0f / l0, inv1 = 1.0f / l1;
#pragma unroll
    for (int nf = 0; nf < 8; nf++) {
        int c = h * DH + nf * 8 + cc * 2;
        size_t o0 = ((size_t)r0g * BZ + b) * D + c;
        size_t o1 = ((size_t)r1g * BZ + b) * D + c;
        float2 q0 = *(const float2*)&q[o0];
        float2 q1 = *(const float2*)&q[o1];
        *(float2*)&out[o0] = make_float2(q0.x + Oacc[nf][0] * inv0,
                                         q0.y + Oacc[nf][1] * inv0);
        *(float2*)&out[o1] = make_float2(q1.x + Oacc[nf][2] * inv1,
                                         q1.y + Oacc[nf][3] * inv1);
    }
}

// ---------------- launch ----------------------------------------------------
extern "C" void kernel_launch(void* const* d_in, const int* in_sizes, int n_in,
                              void* d_out, int out_size) {
    const float* query = (const float*)d_in[0];
    const float* seg   = (const float*)d_in[1];
    const float* Wq    = (const float*)d_in[2];
    const float* bq    = (const float*)d_in[3];
    const float* Wk    = (const float*)d_in[4];
    const float* bk    = (const float*)d_in[5];
    const float* Wv    = (const float*)d_in[6];
    const float* bv    = (const float*)d_in[7];
    float* out = (float*)d_out;

    const int PM_SMEM = 4 * CHUNK_BYTES;   // 73728 -> 2 blocks/SM
    cudaFuncSetAttribute(pm_kernel, cudaFuncAttributeMaxDynamicSharedMemorySize, PM_SMEM);
    cudaFuncSetAttribute(flash_kernel, cudaFuncAttributeMaxDynamicSharedMemorySize,
                         FSM_BYTES);

    prep_kernel<<<4864, 256>>>(query, Wq, Wk, Wv);
    pm_kernel<<<1056, 256, PM_SMEM>>>(seg, bq, bk, bv);
    flash_kernel<<<dim3(8, 64), 256, FSM_BYTES>>>(query, out);
}

// round 17
// speedup vs baseline: 1.5158x; 1.5158x over previous
#include <cuda_runtime.h>
#include <cuda_fp16.h>
#include <math.h>
#include <stdint.h>

#define LQ 1024
#define BZ 8
#define D  512
#define NH 8
#define DH 64
#define IOU_THR 0.2f
#define COS_THR 0.2f
#define NEGF -3.402823466e38f

#define SSTRH 72  // fp16 stride (halves): 144B -> LDSM conflict-free

// ---------------- scratch (static device globals; no allocations) ----------
__device__ __half g_hh[(size_t)BZ * LQ * D];          // fp16 h (proj A + mask A/B)
__device__ __half g_Wh[3 * 512 * 512];                // fp16 Wq|Wk|Wv
__device__ __half g_Qh[(size_t)BZ * LQ * D];
__device__ __half g_Kh[(size_t)BZ * LQ * D];
__device__ __half g_Vth[(size_t)BZ * NH * DH * LQ];   // [bh][dh][Lq]
__device__ float  g_norm[BZ * LQ];
__device__ unsigned char g_mask[(size_t)BZ * LQ * LQ];
__device__ unsigned char g_live[BZ * 8 * 16];

__device__ __forceinline__ uint32_t smem_u32(const void* p) {
    uint32_t a;
    asm("{ .reg .u64 t; cvta.to.shared.u64 t, %1; cvt.u32.u64 %0, t; }"
        : "=r"(a) : "l"(p));
    return a;
}
__device__ __forceinline__ uint32_t pack_h2(float lo, float hi) {
    __half2 h = __floats2half2_rn(lo, hi);
    return *(uint32_t*)&h;
}

#define MMA_F16(c0, c1, c2, c3, a0, a1, a2, a3, b0, b1) \
    asm volatile("mma.sync.aligned.m16n8k16.row.col.f32.f16.f16.f32 " \
        "{%0,%1,%2,%3}, {%4,%5,%6,%7}, {%8,%9}, {%0,%1,%2,%3};" \
        : "+f"(c0), "+f"(c1), "+f"(c2), "+f"(c3) \
        : "r"(a0), "r"(a1), "r"(a2), "r"(a3), "r"(b0), "r"(b1))

#define LDSM_X4(d0, d1, d2, d3, addr) \
    asm volatile("ldmatrix.sync.aligned.m8n8.x4.shared.b16 {%0,%1,%2,%3}, [%4];" \
        : "=r"(d0), "=r"(d1), "=r"(d2), "=r"(d3) : "r"(addr))

#define CPASYNC16(dst, src) \
    asm volatile("cp.async.ca.shared.global [%0], [%1], 16;" \
                 :: "r"(dst), "l"(src) : "memory")
#define CPCOMMIT() asm volatile("cp.async.commit_group;" ::: "memory")
#define CPWAIT(n)  asm volatile("cp.async.wait_group %0;" :: "n"(n) : "memory")

__device__ __forceinline__ float warp_sum(float v) {
#pragma unroll
    for (int o = 16; o > 0; o >>= 1) v += __shfl_xor_sync(0xffffffffu, v, o);
    return v;
}

#define CHUNK_BYTES 18432   // 128 rows * 72 halves * 2B

// ==================== fp16 GEMM core (K64 chunks, 2-stage) ==================
__device__ __forceinline__ void mma_chunk_h(uint32_t As_u, uint32_t Bs_u,
                                            int wm, int wn, int lane,
                                            float (&acc)[4][4][4]) {
    const uint32_t a_base = As_u +
        ((wm * 64 + (lane & 15)) * SSTRH + ((lane >> 4) & 1) * 8) * 2;
    const uint32_t b_base = Bs_u +
        (((wn * 4 + ((lane >> 4) & 1)) * 8 + (lane & 7)) * SSTRH + ((lane >> 3) & 1) * 8) * 2;
#pragma unroll
    for (int ks = 0; ks < 4; ks++) {       // each ks = k16
        uint32_t a[4][4];
#pragma unroll
        for (int mf = 0; mf < 4; mf++)
            LDSM_X4(a[mf][0], a[mf][1], a[mf][2], a[mf][3],
                    a_base + (mf * 16 * SSTRH) * 2 + ks * 32);
        uint32_t bfr[2][4];
#pragma unroll
        for (int p = 0; p < 2; p++)
            LDSM_X4(bfr[p][0], bfr[p][1], bfr[p][2], bfr[p][3],
                    b_base + (p * 16 * SSTRH) * 2 + ks * 32);
#pragma unroll
        for (int mf = 0; mf < 4; mf++)
#pragma unroll
            for (int nf = 0; nf < 4; nf++)
                MMA_F16(acc[mf][nf][0], acc[mf][nf][1], acc[mf][nf][2], acc[mf][nf][3],
                        a[mf][0], a[mf][1], a[mf][2], a[mf][3],
                        bfr[nf >> 1][(nf & 1) * 2], bfr[nf >> 1][(nf & 1) * 2 + 1]);
    }
}

__device__ __forceinline__ void issue_chunk_h(uint32_t base,
                                              const __half* __restrict__ Ab, int Astr,
                                              const __half* __restrict__ Bb, int Bstr,
                                              int it, int tid) {
    const int p = it & 1;
    const uint32_t aoff = base + (uint32_t)(p * CHUNK_BYTES);
    const uint32_t boff = base + (uint32_t)((2 + p) * CHUNK_BYTES);
#pragma unroll
    for (int i = 0; i < 4; i++) {
        int idx = tid + i * 256;
        int r = idx >> 3, c8 = idx & 7;
        CPASYNC16(aoff + (r * SSTRH + c8 * 8) * 2, Ab + (size_t)r * Astr + it * 64 + c8 * 8);
        CPASYNC16(boff + (r * SSTRH + c8 * 8) * 2, Bb + (size_t)r * Bstr + it * 64 + c8 * 8);
    }
}

template <int NCH>
__device__ __forceinline__ void gemm_h(const __half* __restrict__ Ab, int Astr,
                                       const __half* __restrict__ Bb, int Bstr,
                                       float* smem, float (&acc)[4][4][4]) {
    const int tid = threadIdx.x;
    const int w = tid >> 5, lane = tid & 31;
    const int wm = w & 1, wn = w >> 1;
    const uint32_t base = smem_u32(smem);
    issue_chunk_h(base, Ab, Astr, Bb, Bstr, 0, tid);
    CPCOMMIT();
    for (int it = 0; it < NCH; ++it) {
        const int p = it & 1;
        CPWAIT(0);
        __syncthreads();
        if (it + 1 < NCH) {
            issue_chunk_h(base, Ab, Astr, Bb, Bstr, it + 1, tid);
            CPCOMMIT();
        }
        mma_chunk_h(base + p * CHUNK_BYTES, base + (2 + p) * CHUNK_BYTES,
                    wm, wn, lane, acc);
    }
    __syncthreads();
}

// ---------------- prep: norms + fp16 h + fp16 W -----------------------------
__global__ void prep_kernel(const float* __restrict__ q,
                            const float* __restrict__ Wq,
                            const float* __restrict__ Wk,
                            const float* __restrict__ Wv) {
    const int bid = blockIdx.x, tid = threadIdx.x;
    if (bid < 4096) {
        const int half_ = tid >> 7;
        const int t = tid & 127;
        const int row = bid * 2 + half_;
        const int b = row >> 10, l = row & 1023;
        const size_t o = ((size_t)l * BZ + b) * D + t * 4;
        float4 v = *(const float4*)(q + o);
        *(__half2*)(g_hh + o)     = __floats2half2_rn(v.x, v.y);
        *(__half2*)(g_hh + o + 2) = __floats2half2_rn(v.z, v.w);
        float s = v.x * v.x + v.y * v.y + v.z * v.z + v.w * v.w;
        s = warp_sum(s);
        __shared__ float red[8];
        if ((t & 31) == 0) red[half_ * 4 + (t >> 5)] = s;
        __syncthreads();
        if (t == 0) {
            float tot = red[half_ * 4] + red[half_ * 4 + 1] +
                        red[half_ * 4 + 2] + red[half_ * 4 + 3];
            g_norm[row] = fmaxf(sqrtf(tot), 1e-8f);
        }
    } else {
        const int idx = (bid - 4096) * 256 + tid;
        const int which = idx >> 16;
        const int off = (idx & 65535) * 4;
        const float* W = (which == 0) ? Wq : (which == 1) ? Wk : Wv;
        float4 v = *(const float4*)(W + off);
        __half* dst = g_Wh + which * 262144 + off;
        *(__half2*)(dst)     = __floats2half2_rn(v.x, v.y);
        *(__half2*)(dst + 2) = __floats2half2_rn(v.z, v.w);
    }
}

// ================ fused proj (bid<768) + mask (bid>=768), all fp16 ==========
__global__ __launch_bounds__(256, 2) void pm_kernel(
    const float* __restrict__ seg,
    const float* __restrict__ bq, const float* __restrict__ bk, const float* __restrict__ bv) {
    extern __shared__ float smp[];
    const int tid = threadIdx.x;
    const int w = tid >> 5, lane = tid & 31;
    const int wm = w & 1, wn = w >> 1;
    const int bid = blockIdx.x;

    if (bid < 768) {   // ---------------- projection path ----------------
        const int which = bid >> 8;
        const int rem = bid & 255;
        const int col0 = (rem & 3) * 128;
        const int y = rem >> 2;
        const int b = y >> 3;
        const int i0 = (y & 7) * 128;
        const float* bias = (which == 0) ? bq : (which == 1) ? bk : bv;

        float acc[4][4][4] = {};
        const __half* Ab = g_hh + (size_t)i0 * (BZ * D) + (size_t)b * D;
        const __half* Bb = g_Wh + which * 262144 + (size_t)col0 * D;
        gemm_h<D / 64>(Ab, BZ * D, Bb, D, smp, acc);

        const int rbase = wm * 64 + (lane >> 2);
        const int cbase = wn * 32 + (lane & 3) * 2;
        if (which < 2) {
            __half* out = (which == 0) ? g_Qh : g_Kh;
#pragma unroll
            for (int mf = 0; mf < 4; mf++) {
                int r0 = i0 + rbase + mf * 16;
#pragma unroll
                for (int nf = 0; nf < 4; nf++) {
                    int c = col0 + cbase + nf * 8;
                    float2 bb = *(const float2*)&bias[c];
                    *(__half2*)&out[((size_t)(b * LQ + r0)) * D + c] =
                        __floats2half2_rn(acc[mf][nf][0] + bb.x, acc[mf][nf][1] + bb.y);
                    *(__half2*)&out[((size_t)(b * LQ + r0 + 8)) * D + c] =
                        __floats2half2_rn(acc[mf][nf][2] + bb.x, acc[mf][nf][3] + bb.y);
                }
            }
        } else {
#pragma unroll
            for (int mf = 0; mf < 4; mf++) {
                int r0 = i0 + rbase + mf * 16;
#pragma unroll
                for (int nf = 0; nf < 4; nf++) {
                    int n = col0 + cbase + nf * 8;
                    float2 bb = *(const float2*)&bias[n];
                    size_t o0 = ((size_t)(b * NH + (n >> 6)) * DH + (n & 63)) * LQ;
                    size_t o1 = ((size_t)(b * NH + ((n + 1) >> 6)) * DH + ((n + 1) & 63)) * LQ;
                    g_Vth[o0 + r0]     = __float2half_rn(acc[mf][nf][0] + bb.x);
                    g_Vth[o1 + r0]     = __float2half_rn(acc[mf][nf][1] + bb.y);
                    g_Vth[o0 + r0 + 8] = __float2half_rn(acc[mf][nf][2] + bb.x);
                    g_Vth[o1 + r0 + 8] = __float2half_rn(acc[mf][nf][3] + bb.y);
                }
            }
        }
    } else {   // -------- mask path (fp16): I<=J triangle -------------------
        const int mb = bid - 768;
        const int b = mb / 36;
        int t = mb % 36;
        int I = 0;
        while (t >= 8 - I) { t -= 8 - I; I++; }
        const int J = I + t;
        const int i0 = I * 128, j0 = J * 128;

        float acc[4][4][4] = {};
        const __half* Ab = g_hh + (size_t)i0 * (BZ * D) + (size_t)b * D;
        const __half* Bb = g_hh + (size_t)j0 * (BZ * D) + (size_t)b * D;
        gemm_h<D / 64>(Ab, BZ * D, Bb, BZ * D, smp, acc);

        __shared__ unsigned int liveflag[4];   // [0,1]=col halves, [2,3]=row halves
        if (tid < 4) liveflag[tid] = 0;
        __syncthreads();

        float4* auxr = (float4*)smp;
        float4* auxc = (float4*)(smp + 512);
        unsigned char* sT = (unsigned char*)(smp + 2048);   // 128 x 144 transpose tile
        const float* sgb = seg + (size_t)b * LQ * 2;
        if (tid < 128) {
            int r = i0 + tid;
            float2 sg = *(const float2*)(sgb + r * 2);
            auxr[tid] = make_float4(g_norm[b * LQ + r], sg.x - 0.5f * sg.y,
                                    sg.x + 0.5f * sg.y, sg.y);
        } else {
            int tt = tid - 128;
            int c = j0 + tt;
            float2 sg = *(const float2*)(sgb + c * 2);
            auxc[tt] = make_float4(g_norm[b * LQ + c], sg.x - 0.5f * sg.y,
                                   sg.x + 0.5f * sg.y, sg.y);
        }
        __syncthreads();

        const int rbase = wm * 64 + (lane >> 2);
        const int cbase = wn * 32 + (lane & 3) * 2;
        unsigned int any = 0;
#pragma unroll
        for (int mf = 0; mf < 4; mf++) {
#pragma unroll
            for (int half_ = 0; half_ < 2; half_++) {
                int rl_ = rbase + mf * 16 + half_ * 8;
                float4 ar = auxr[rl_];
                int rg = i0 + rl_;
#pragma unroll
                for (int nf = 0; nf < 4; nf++) {
                    int cl_ = cbase + nf * 8;
                    uchar2 mm;
#pragma unroll
                    for (int e = 0; e < 2; e++) {
                        float4 ac = auxc[cl_ + e];
                        float cosv = acc[mf][nf][half_ * 2 + e] / (ar.x * ac.x);
                        float inter = fmaxf(fminf(ar.z, ac.z) - fmaxf(ar.y, ac.y), 0.f);
                        float iou = inter / (ar.w + ac.w - inter);
                        int cg = j0 + cl_ + e;
                        bool adj = (cosv > COS_THR) && ((iou <= IOU_THR) || (rg == cg));
                        any |= (unsigned)adj;
                        unsigned char mv = adj ? 0 : 1;
                        if (e == 0) mm.x = mv; else mm.y = mv;
                        sT[(cl_ + e) * 144 + rl_] = mv;
                    }
                    *(uchar2*)&g_mask[((size_t)(b * LQ + rg)) * LQ + j0 + cl_] = mm;
                }
            }
        }
        if (any) {
            atomicOr(&liveflag[wn >> 1], 1u);
            atomicOr(&liveflag[2 + wm], 1u);
        }
        __syncthreads();

        // transposed block write-out: only if the tile has ANY adjacency
        // (flash gates all mask reads on g_live flags, so bytes of dead
        // tiles are never observed -> exact skip)
        const unsigned int tile_any = liveflag[0] | liveflag[1] |
                                      liveflag[2] | liveflag[3];
        if (I != J && tile_any) {
#pragma unroll
            for (int i = 0; i < 4; i++) {
                int idx = tid + i * 256;
                int c = idx >> 3, g = idx & 7;
                *(uint4*)&g_mask[((size_t)(b * LQ + j0 + c)) * LQ + i0 + g * 16] =
                    *(const uint4*)&sT[c * 144 + g * 16];
            }
        }
        if (I != J && tid < 2)
            g_live[(b * 8 + J) * 16 + I * 2 + tid] = (unsigned char)liveflag[2 + tid];
        if (tid < 2)
            g_live[(b * 8 + I) * 16 + J * 2 + tid] = (unsigned char)liveflag[tid];
    }
}

// ==================== fused attention (fp16 flash) ==========================
// smem halves: sQ[0,9216) sK0[9216,13824) sK1[13824,18432) sV0[18432,23040) sV1[23040,27648)
#define FSM_BYTES (27648 * 2)

__device__ __forceinline__ void issue_kv(__half* smh, int p, int jt,
                                         int b, int bh, int h, int tid) {
    const int j0 = jt * 64;
    const uint32_t koff = smem_u32(smh + 9216 + p * 4608);
    const uint32_t voff = smem_u32(smh + 18432 + p * 4608);
#pragma unroll
    for (int i = 0; i < 2; i++) {
        int idx = tid + i * 256;
        int r = idx >> 3, g = idx & 7;
        CPASYNC16(koff + (r * SSTRH + g * 8) * 2,
                  g_Kh + ((size_t)(b * LQ + j0 + r)) * D + h * DH + g * 8);
        CPASYNC16(voff + (r * SSTRH + g * 8) * 2,
                  g_Vth + ((size_t)bh * DH + r) * LQ + j0 + g * 8);
    }
}

__global__ __launch_bounds__(256, 2) void flash_kernel(const float* __restrict__ q,
                                                       float* __restrict__ out) {
    extern __shared__ __half smh[];
    const int tid = threadIdx.x;
    const int w = tid >> 5, lane = tid & 31;
    const int rr = lane >> 2, cc = lane & 3;
    const int bh = blockIdx.y, b = bh >> 3, h = bh & 7;
    const int i0 = blockIdx.x * 128;
    const int wbase = w * 16;

    __shared__ int s_list[16];
    __shared__ int s_nlive;

    // stage Q via cp.async — overlaps the live-list ballot
    {
        const uint32_t qoff = smem_u32(smh);
#pragma unroll
        for (int i = 0; i < 4; i++) {
            int idx = tid + i * 256;
            int r = idx >> 3, g = idx & 7;
            CPASYNC16(qoff + (r * SSTRH + g * 8) * 2,
                      g_Qh + ((size_t)(b * LQ + i0 + r)) * D + h * DH + g * 8);
        }
        CPCOMMIT();
    }
    if (w == 0) {
        unsigned f = 0;
        if (lane < 16) f = g_live[(b * 8 + (i0 >> 7)) * 16 + lane];
        unsigned bal = __ballot_sync(0xffffffffu, f != 0) & 0xffffu;
        if (lane < 16 && f) s_list[__popc(bal & ((1u << lane) - 1))] = lane;
        if (lane == 0) s_nlive = __popc(bal);
    }
    __syncthreads();
    const int nlive = s_nlive;

    const uint32_t q_base = smem_u32(smh) +
        ((wbase + (lane & 15)) * SSTRH + ((lane >> 4) & 1) * 8) * 2;
    const uint32_t fb = ((((lane >> 4) & 1) * 8 + (lane & 7)) * SSTRH +
                         ((lane >> 3) & 1) * 8) * 2;
    const uint32_t k_base0 = smem_u32(smh + 9216) + fb;
    const uint32_t v_base0 = smem_u32(smh + 18432) + fb;

    float Oacc[8][4] = {};
    float m0 = NEGF, m1 = NEGF, l0 = 0.f, l1 = 0.f;
    const int r0g = i0 + wbase + rr, r1g = r0g + 8;
    const unsigned char* mrow0 = g_mask + ((size_t)(b * LQ + r0g)) * LQ;
    const unsigned char* mrow1 = g_mask + ((size_t)(b * LQ + r1g)) * LQ;

    issue_kv(smh, 0, s_list[0], b, bh, h, tid);
    CPCOMMIT();

    for (int li = 0; li < nlive; li++) {
        const int p = li & 1;
        const int j0 = s_list[li] * 64;
        if (li + 1 < nlive) {
            issue_kv(smh, p ^ 1, s_list[li + 1], b, bh, h, tid);
            CPCOMMIT();
            CPWAIT(1);
        } else {
            CPWAIT(0);
        }
        __syncthreads();
        const uint32_t k_base = k_base0 + p * 9216;   // 4608 halves
        const uint32_t v_base = v_base0 + p * 9216;

        // S = Q K^T (fp16 m16n8k16)
        float Sacc[8][4] = {};
#pragma unroll
        for (int ks = 0; ks < 4; ks++) {
            uint32_t a0, a1, a2, a3;
            LDSM_X4(a0, a1, a2, a3, q_base + ks * 32);
#pragma unroll
            for (int pp = 0; pp < 4; pp++) {
                uint32_t f0, f1, f2, f3;
                LDSM_X4(f0, f1, f2, f3, k_base + pp * (16 * SSTRH * 2) + ks * 32);
                MMA_F16(Sacc[pp * 2][0], Sacc[pp * 2][1], Sacc[pp * 2][2], Sacc[pp * 2][3],
                        a0, a1, a2, a3, f0, f1);
                MMA_F16(Sacc[pp * 2 + 1][0], Sacc[pp * 2 + 1][1],
                        Sacc[pp * 2 + 1][2], Sacc[pp * 2 + 1][3],
                        a0, a1, a2, a3, f2, f3);
            }
        }

        // scale + mask + tile row max
        float mx0 = NEGF, mx1 = NEGF;
#pragma unroll
        for (int nf = 0; nf < 8; nf++) {
            int c = j0 + nf * 8 + cc * 2;
            uchar2 ma = *(const uchar2*)&mrow0[c];
            uchar2 mb = *(const uchar2*)&mrow1[c];
            Sacc[nf][0] = ma.x ? NEGF : Sacc[nf][0] * 0.125f;
            Sacc[nf][1] = ma.y ? NEGF : Sacc[nf][1] * 0.125f;
            Sacc[nf][2] = mb.x ? NEGF : Sacc[nf][2] * 0.125f;
            Sacc[nf][3] = mb.y ? NEGF : Sacc[nf][3] * 0.125f;
            mx0 = fmaxf(mx0, fmaxf(Sacc[nf][0], Sacc[nf][1]));
            mx1 = fmaxf(mx1, fmaxf(Sacc[nf][2], Sacc[nf][3]));
        }
        mx0 = fmaxf(mx0, __shfl_xor_sync(0xffffffffu, mx0, 1));
        mx0 = fmaxf(mx0, __shfl_xor_sync(0xffffffffu, mx0, 2));
        mx1 = fmaxf(mx1, __shfl_xor_sync(0xffffffffu, mx1, 1));
        mx1 = fmaxf(mx1, __shfl_xor_sync(0xffffffffu, mx1, 2));

        float nm0 = fmaxf(m0, mx0), nm1 = fmaxf(m1, mx1);
        float al0 = __expf(m0 - nm0), al1 = __expf(m1 - nm1);
        m0 = nm0; m1 = nm1;

        float rs0 = 0.f, rs1 = 0.f;
#pragma unroll
        for (int nf = 0; nf < 8; nf++) {
            float p00 = __expf(Sacc[nf][0] - nm0);
            float p01 = __expf(Sacc[nf][1] - nm0);
            float p10 = __expf(Sacc[nf][2] - nm1);
            float p11 = __expf(Sacc[nf][3] - nm1);
            rs0 += p00 + p01; rs1 += p10 + p11;
            Sacc[nf][0] = p00; Sacc[nf][1] = p01;
            Sacc[nf][2] = p10; Sacc[nf][3] = p11;
            Oacc[nf][0] *= al0; Oacc[nf][1] *= al0;
            Oacc[nf][2] *= al1; Oacc[nf][3] *= al1;
        }
        rs0 += __shfl_xor_sync(0xffffffffu, rs0, 1);
        rs0 += __shfl_xor_sync(0xffffffffu, rs0, 2);
        rs1 += __shfl_xor_sync(0xffffffffu, rs1, 1);
        rs1 += __shfl_xor_sync(0xffffffffu, rs1, 2);
        l0 = l0 * al0 + rs0;
        l1 = l1 * al1 + rs1;

        // O += P @ V : P packed to fp16 in registers; V frags via ldmatrix
#pragma unroll
        for (int ks = 0; ks < 4; ks++) {
            uint32_t a0 = pack_h2(Sacc[ks * 2][0], Sacc[ks * 2][1]);
            uint32_t a1 = pack_h2(Sacc[ks * 2][2], Sacc[ks * 2][3]);
            uint32_t a2 = pack_h2(Sacc[ks * 2 + 1][0], Sacc[ks * 2 + 1][1]);
            uint32_t a3 = pack_h2(Sacc[ks * 2 + 1][2], Sacc[ks * 2 + 1][3]);
#pragma unroll
            for (int pp = 0; pp < 4; pp++) {
                uint32_t f0, f1, f2, f3;
                LDSM_X4(f0, f1, f2, f3, v_base + pp * (16 * SSTRH * 2) + ks * 32);
                MMA_F16(Oacc[pp * 2][0], Oacc[pp * 2][1], Oacc[pp * 2][2], Oacc[pp * 2][3],
                        a0, a1, a2, a3, f0, f1);
                MMA_F16(Oacc[pp * 2 + 1][0], Oacc[pp * 2 + 1][1],
                        Oacc[pp * 2 + 1][2], Oacc[pp * 2 + 1][3],
                        a0, a1, a2, a3, f2, f3);
            }
        }
        if (li + 2 < nlive) __syncthreads();
    }

    // epilogue
    float inv0 = 1.0f / l0, inv1 = 1.0f / l1;
#pragma unroll
    for (int nf = 0; nf < 8; nf++) {
        int c = h * DH + nf * 8 + cc * 2;
        size_t o0 = ((size_t)r0g * BZ + b) * D + c;
        size_t o1 = ((size_t)r1g * BZ + b) * D + c;
        float2 q0 = *(const float2*)&q[o0];
        float2 q1 = *(const float2*)&q[o1];
        *(float2*)&out[o0] = make_float2(q0.x + Oacc[nf][0] * inv0,
                                         q0.y + Oacc[nf][1] * inv0);
        *(float2*)&out[o1] = make_float2(q1.x + Oacc[nf][2] * inv1,
                                         q1.y + Oacc[nf][3] * inv1);
    }
}

// ---------------- launch ----------------------------------------------------
extern "C" void kernel_launch(void* const* d_in, const int* in_sizes, int n_in,
                              void* d_out, int out_size) {
    const float* query = (const float*)d_in[0];
    const float* seg   = (const float*)d_in[1];
    const float* Wq    = (const float*)d_in[2];
    const float* bq    = (const float*)d_in[3];
    const float* Wk    = (const float*)d_in[4];
    const float* bk    = (const float*)d_in[5];
    const float* Wv    = (const float*)d_in[6];
    const float* bv    = (const float*)d_in[7];
    float* out = (float*)d_out;

    const int PM_SMEM = 4 * CHUNK_BYTES;   // 73728 -> 2 blocks/SM
    cudaFuncSetAttribute(pm_kernel, cudaFuncAttributeMaxDynamicSharedMemorySize, PM_SMEM);
    cudaFuncSetAttribute(flash_kernel, cudaFuncAttributeMaxDynamicSharedMemorySize,
                         FSM_BYTES);

    prep_kernel<<<4864, 256>>>(query, Wq, Wk, Wv);
    pm_kernel<<<1056, 256, PM_SMEM>>>(seg, bq, bk, bv);
    flash_kernel<<<dim3(8, 64), 256, FSM_BYTES>>>(query, out);
}